// round 16
// baseline (speedup 1.0000x reference)
#include <cuda_runtime.h>
#include <cuda_bf16.h>
#include <cuda_fp16.h>
#include <math_constants.h>
#include <cstdint>

#define S_LEN  2048
#define HIDDEN 4096
#define NH     32
#define NKV    8
#define HD     96
#define GROUPS 4
#define QDIM   (NH * HD)    // 3072
#define KVDIM  (NKV * HD)   // 768
#define DFULL  128
#define ATT_SCALE 0.08838834764831845f  // 128^-0.5

#define KP_QKV HIDDEN         // 4096 (fp16 1-term)
#define KP_O   QDIM           // 3072 (fp16 1-term)

// ---------------- scratch (allocation-free: device globals) ----------------
static __device__ __align__(256) float g_Q [S_LEN * QDIM];
static __device__ __align__(256) float g_K [S_LEN * KVDIM];
static __device__ __align__(256) float g_V [S_LEN * KVDIM];

static __device__ __align__(256) __half g_hsb[S_LEN * KP_QKV];   // flat h
static __device__ __align__(256) __half g_wqb[QDIM * KP_QKV];    // flat h
static __device__ __align__(256) __half g_wkb[KVDIM * KP_QKV];
static __device__ __align__(256) __half g_wvb[KVDIM * KP_QKV];
static __device__ __align__(256) __half g_aob[S_LEN * KP_O];     // flat h
static __device__ __align__(256) __half g_wob[HIDDEN * KP_O];    // flat h

// flash operands (all fp16; Q keeps hi/lo)
static __device__ __align__(256) __half g_Qh[S_LEN * QDIM];
static __device__ __align__(256) __half g_Ql[S_LEN * QDIM];
static __device__ __align__(256) __half g_Kh[S_LEN * KVDIM];
static __device__ __align__(256) __half g_Vh[S_LEN * KVDIM];

// ---------------------------------------------------------------------------
// PTX helpers
// ---------------------------------------------------------------------------
__device__ __forceinline__ uint32_t smem_u32(const void* p) {
    uint32_t a;
    asm("{ .reg .u64 t; cvta.to.shared.u64 t, %1; cvt.u32.u64 %0, t; }" : "=r"(a) : "l"(p));
    return a;
}
#define CP_ASYNC16(dst, src) asm volatile("cp.async.cg.shared.global [%0], [%1], 16;" :: "r"(dst), "l"(src))
#define CP_COMMIT()          asm volatile("cp.async.commit_group;" ::: "memory")
#define CP_WAIT(n)           asm volatile("cp.async.wait_group %0;" :: "n"(n) : "memory")

#define LDSM_X4(r0, r1, r2, r3, addr)                                            \
    asm volatile("ldmatrix.sync.aligned.m8n8.x4.shared.b16 {%0,%1,%2,%3}, [%4];" \
        : "=r"(r0), "=r"(r1), "=r"(r2), "=r"(r3) : "r"(addr))

#define LDSM_X4_T(r0, r1, r2, r3, addr)                                                \
    asm volatile("ldmatrix.sync.aligned.m8n8.x4.trans.shared.b16 {%0,%1,%2,%3}, [%4];" \
        : "=r"(r0), "=r"(r1), "=r"(r2), "=r"(r3) : "r"(addr))

__device__ __forceinline__ void mma_f16(float* c, uint32_t a0, uint32_t a1,
                                        uint32_t a2, uint32_t a3,
                                        uint32_t b0, uint32_t b1) {
    asm volatile(
        "mma.sync.aligned.m16n8k16.row.col.f32.f16.f16.f32 "
        "{%0,%1,%2,%3}, {%4,%5,%6,%7}, {%8,%9}, {%0,%1,%2,%3};"
        : "+f"(c[0]), "+f"(c[1]), "+f"(c[2]), "+f"(c[3])
        : "r"(a0), "r"(a1), "r"(a2), "r"(a3), "r"(b0), "r"(b1));
}

// ---------------------------------------------------------------------------
// fp16 HMMA GEMM.
// BM=128, BN=256, BK=64, 2-stage cp.async pipeline, 8 warps (2m x 4n),
// warp tile 64x64. launch_bounds(256,2) -> 2 CTAs/SM = 4 warps/SMSP.
// Segmented over N (up to 3 segments). Single-wave grids.
// ---------------------------------------------------------------------------
#define BM 128
#define BN 256
#define BKE 64
#define ROW_B 144
#define A_BYTES (BM * ROW_B)               // 18432
#define B_BYTES (BN * ROW_B)               // 36864
#define STAGE_BYTES (A_BYTES + B_BYTES)    // 55296
#define NSTAGE 2
#define GEMM_SMEM (NSTAGE * STAGE_BYTES)   // 110592

__device__ __forceinline__ void load_tiles(uint32_t stage_base,
    const __half* __restrict__ A, const __half* __restrict__ B,
    int bm, int bn, int kc, int Kp, int tid)
{
    const char* Ag = (const char*)(A + (size_t)bm * Kp + kc * BKE);
    const char* Bg = (const char*)(B + (size_t)bn * Kp + kc * BKE);
    const size_t rowb = (size_t)Kp * 2;
    const uint32_t sA = stage_base;
    const uint32_t sB = stage_base + A_BYTES;
#pragma unroll
    for (int i = 0; i < 4; i++) {          // A: 128 rows x 8 segs, 256 threads
        int idx = tid + i * 256;
        int row = idx >> 3, seg = idx & 7;
        CP_ASYNC16(sA + row * ROW_B + seg * 16, Ag + (size_t)row * rowb + seg * 16);
    }
#pragma unroll
    for (int i = 0; i < 8; i++) {          // B: 256 rows x 8 segs
        int idx = tid + i * 256;
        int row = idx >> 3, seg = idx & 7;
        CP_ASYNC16(sB + row * ROW_B + seg * 16, Bg + (size_t)row * rowb + seg * 16);
    }
}

__global__ __launch_bounds__(256, 2) void gemm_mma(
    const __half* __restrict__ A,
    const __half* __restrict__ B0, float* __restrict__ C0, int nt0, int N0,
    const __half* __restrict__ B1, float* __restrict__ C1, int nt1, int N1,
    const __half* __restrict__ B2, float* __restrict__ C2, int N2,
    int Kp)
{
    extern __shared__ char smem[];
    const uint32_t sbase = smem_u32(smem);
    const int tid  = threadIdx.x;
    const int wid  = tid >> 5;
    const int lane = tid & 31;
    const int bm   = blockIdx.y * BM;
    const int NC   = Kp / BKE;

    int bnt = blockIdx.x;
    const __half* B;
    float* C; int N;
    if (bnt < nt0)            { B = B0; C = C0; N = N0; }
    else if (bnt < nt0 + nt1) { B = B1; C = C1; N = N1; bnt -= nt0; }
    else                      { B = B2; C = C2; N = N2; bnt -= nt0 + nt1; }
    const int bn = bnt * BN;

    const int wm = (wid >> 2) * 64;   // 2m x 4n warp grid
    const int wn = (wid & 3) * 64;

    float acc[4][8][4];
#pragma unroll
    for (int t = 0; t < 4; t++)
#pragma unroll
        for (int j = 0; j < 8; j++)
#pragma unroll
            for (int q = 0; q < 4; q++) acc[t][j][q] = 0.f;

    const int a_row    = ((lane >> 3) & 1) * 8 + (lane & 7);
    const int a_cshift = ((lane >> 4) & 1) * 16;
    const int b_row    = ((lane >> 4) & 1) * 8 + (lane & 7);
    const int b_cshift = ((lane >> 3) & 1) * 16;

    load_tiles(sbase, A, B, bm, bn, 0, Kp, tid); CP_COMMIT();

    for (int c = 0; c < NC; c++) {
        CP_WAIT(0);
        __syncthreads();

        if (c + 1 < NC) {
            load_tiles(sbase + ((c + 1) & 1) * STAGE_BYTES, A, B, bm, bn, c + 1, Kp, tid);
            CP_COMMIT();
        }

        const uint32_t sA = sbase + (c & 1) * STAGE_BYTES;
        const uint32_t sB = sA + A_BYTES;
#pragma unroll
        for (int ks = 0; ks < 4; ks++) {
            uint32_t a[4][4];
#pragma unroll
            for (int t = 0; t < 4; t++) {
                uint32_t addr = sA + (wm + t * 16 + a_row) * ROW_B + ks * 32 + a_cshift;
                LDSM_X4(a[t][0], a[t][1], a[t][2], a[t][3], addr);
            }
#pragma unroll
            for (int p = 0; p < 4; p++) {
                uint32_t b0, b1, b2, b3;
                uint32_t addr = sB + (wn + p * 16 + b_row) * ROW_B + ks * 32 + b_cshift;
                LDSM_X4(b0, b1, b2, b3, addr);
#pragma unroll
                for (int t = 0; t < 4; t++) {
                    mma_f16(acc[t][2 * p],     a[t][0], a[t][1], a[t][2], a[t][3], b0, b1);
                    mma_f16(acc[t][2 * p + 1], a[t][0], a[t][1], a[t][2], a[t][3], b2, b3);
                }
            }
        }
    }

#pragma unroll
    for (int t = 0; t < 4; t++) {
        const int r0 = bm + wm + t * 16 + (lane >> 2);
#pragma unroll
        for (int j = 0; j < 8; j++) {
            const int col = bn + wn + j * 8 + (lane & 3) * 2;
            float* c0 = C + (size_t)r0 * N + col;
            float* c1 = C + (size_t)(r0 + 8) * N + col;
            *(float2*)c0 = make_float2(acc[t][j][0], acc[t][j][1]);
            *(float2*)c1 = make_float2(acc[t][j][2], acc[t][j][3]);
        }
    }
}

// ---------------------------------------------------------------------------
// Fused flat fp32 -> fp16 conversions over 5 regions, float4-vectorized.
// ---------------------------------------------------------------------------
__global__ void split_all(const float* __restrict__ x0, __half* y0, int n0,
                          const float* __restrict__ x1, __half* y1, int n1,
                          const float* __restrict__ x2, __half* y2, int n2,
                          const float* __restrict__ x3, __half* y3, int n3,
                          const float* __restrict__ x4, __half* y4, int n4)
{
    int t = blockIdx.x * blockDim.x + threadIdx.x;   // quad index
    const float* X; __half* Y;
    if      (t < n0)         { X = x0; Y = y0; }
    else if ((t -= n0) < n1) { X = x1; Y = y1; }
    else if ((t -= n1) < n2) { X = x2; Y = y2; }
    else if ((t -= n2) < n3) { X = x3; Y = y3; }
    else if ((t -= n3) < n4) { X = x4; Y = y4; }
    else return;
    float4 x = ((const float4*)X)[t];
    __half2 h0 = __floats2half2_rn(x.x, x.y);
    __half2 h1 = __floats2half2_rn(x.z, x.w);
    uint2 v;
    v.x = *(uint32_t*)&h0;
    v.y = *(uint32_t*)&h1;
    ((uint2*)Y)[t] = v;
}

// ---------------------------------------------------------------------------
// Fused indexed RoPE (fp16 out) + V fp16 convert, one launch.
// Q: hi/lo fp16 split (scaled); K: hi only.
// ---------------------------------------------------------------------------
__device__ __forceinline__ void do_rope(const float* X,
                                        __half* Xh, __half* Xl, bool write_lo,
                                        const float* cosT, const float* sinT,
                                        const int* idx, int nheads, int group,
                                        float scale, int t)
{
    int d = t % 48;
    int h = (t / 48) % nheads;
    int s = t / (48 * nheads);
    int hk = h / group;

    const float* base = X + (size_t)s * (nheads * HD) + h * HD;
    float x1 = base[d];
    float x2 = base[d + 48];

    int i1 = idx[hk * HD + d];
    int i2 = idx[hk * HD + d + 48];
    float c1 = cosT[s * DFULL + i1], s1 = sinT[s * DFULL + i1];
    float c2 = cosT[s * DFULL + i2], s2 = sinT[s * DFULL + i2];

    float lo = (x1 * c1 - x2 * s1) * scale;
    float hi = (x2 * c2 + x1 * s2) * scale;

    size_t o = (size_t)s * (nheads * HD) + h * HD;
    __half bh = __float2half_rn(lo);
    Xh[o + d] = bh;
    if (write_lo) Xl[o + d] = __float2half_rn(lo - __half2float(bh));
    bh = __float2half_rn(hi);
    Xh[o + d + 48] = bh;
    if (write_lo) Xl[o + d + 48] = __float2half_rn(hi - __half2float(bh));
}

__global__ void rope_split_all(
    const float* __restrict__ Qs, __half* Qh, __half* Ql,
    const float* __restrict__ Ks, __half* Kh,
    const float* __restrict__ Vs, __half* Vh,
    const float* __restrict__ cosT, const float* __restrict__ sinT,
    const int* __restrict__ idx, int totQ, int totK, int totVpairs)
{
    int t = blockIdx.x * blockDim.x + threadIdx.x;
    if (t < totQ) {
        do_rope(Qs, Qh, Ql, true, cosT, sinT, idx, NH, GROUPS, ATT_SCALE, t);
        return;
    }
    t -= totQ;
    if (t < totK) {
        do_rope(Ks, Kh, nullptr, false, cosT, sinT, idx, NKV, 1, 1.0f, t);
        return;
    }
    t -= totK;
    if (t < totVpairs) {
        float2 x = ((const float2*)Vs)[t];
        __half2 h = __floats2half2_rn(x.x, x.y);
        ((uint32_t*)Vh)[t] = *(uint32_t*)&h;
    }
}

// ---------------------------------------------------------------------------
// fp16 HMMA flash attention, causal GQA. CTA = 128 q-rows x 1 head, 8 warps.
// 64-key blocks, double-buffered cp.async KV stages (Kh + Vh fp16).
// S = QhKh + QlKh (merged passes);  O += PhVh.  Flat fp16 AO out.
// ---------------------------------------------------------------------------
#define FD   96
#define FBM  128
#define FBN  64
#define FROW 208
#define FQ_BYTES  (FBM * FROW)
#define FKV_BYTES (FBN * FROW)
#define STG_BYTES (2 * FKV_BYTES)
#define FLASH_SMEM (2 * FQ_BYTES + 2 * STG_BYTES)   // 106496

__device__ __forceinline__ void flash_load_kv(uint32_t st_base,
    const __half* Kh, const __half* Vh, int key0, int hk, int tid)
{
    const size_t goff = (size_t)key0 * (KVDIM * 2) + hk * (FD * 2);
    const char* g0 = (const char*)Kh + goff;
    const char* g1 = (const char*)Vh + goff;
#pragma unroll
    for (int i = 0; i < 3; i++) {
        int idx = tid + i * 256;
        int row = idx / 12, seg = idx - row * 12;
        uint32_t d = st_base + row * FROW + seg * 16;
        size_t go = (size_t)row * (KVDIM * 2) + seg * 16;
        CP_ASYNC16(d,             g0 + go);
        CP_ASYNC16(d + FKV_BYTES, g1 + go);
    }
}

__global__ __launch_bounds__(256, 1) void flash_mma(
    const __half* __restrict__ Qh, const __half* __restrict__ Ql,
    const __half* __restrict__ Kh, const __half* __restrict__ Vh,
    __half* __restrict__ AOs)
{
    extern __shared__ char smem[];
    const uint32_t sb = smem_u32(smem);
    const int tid = threadIdx.x, wid = tid >> 5, lane = tid & 31;
    const int h = blockIdx.y, hk = h / GROUPS;
    const int qbase = ((int)gridDim.x - 1 - (int)blockIdx.x) * FBM;  // heavy first
    const int nb = qbase / FBN + 2;

    const uint32_t sQh_ = sb, sQl_ = sb + FQ_BYTES;
    const uint32_t st0 = sb + 2 * FQ_BYTES;

    {
        const char* gqh = (const char*)(Qh + (size_t)qbase * QDIM + h * FD);
        const char* gql = (const char*)(Ql + (size_t)qbase * QDIM + h * FD);
#pragma unroll
        for (int i = 0; i < 6; i++) {
            int idx = tid + i * 256;
            int row = idx / 12, seg = idx - row * 12;
            uint32_t d = row * FROW + seg * 16;
            size_t go = (size_t)row * (QDIM * 2) + seg * 16;
            CP_ASYNC16(sQh_ + d, gqh + go);
            CP_ASYNC16(sQl_ + d, gql + go);
        }
        flash_load_kv(st0, Kh, Vh, 0, hk, tid);
        CP_COMMIT();
    }

    float oacc[12][4];
#pragma unroll
    for (int j = 0; j < 12; j++)
#pragma unroll
        for (int q = 0; q < 4; q++) oacc[j][q] = 0.f;
    float m0 = -CUDART_INF_F, m1 = -CUDART_INF_F, l0 = 0.f, l1 = 0.f;

    const int a_row = (lane & 7) + ((lane >> 3) & 1) * 8;
    const int a_cs  = ((lane >> 4) & 1) * 16;
    const int b_row = (lane & 7) + ((lane >> 4) & 1) * 8;
    const int b_cs  = ((lane >> 3) & 1) * 16;
    const int t_row = (lane & 7) + ((lane >> 3) & 1) * 8;
    const int t_cs  = ((lane >> 4) & 1) * 16;

    const int qr_lo = qbase + wid * 16;
    const int row0  = qr_lo + (lane >> 2);

    for (int kb = 0; kb < nb; kb++) {
        if (kb + 1 < nb) {
            flash_load_kv(st0 + ((kb + 1) & 1) * STG_BYTES, Kh, Vh,
                          (kb + 1) * FBN, hk, tid);
            CP_COMMIT();
            CP_WAIT(1);
        } else {
            CP_WAIT(0);
        }
        __syncthreads();

        const int key0 = kb * FBN;
        if (key0 <= qr_lo + 15) {
            const uint32_t sKh_ = st0 + (kb & 1) * STG_BYTES;
            const uint32_t sVh_ = sKh_ + FKV_BYTES;

            float sacc[8][4];
#pragma unroll
            for (int j = 0; j < 8; j++)
#pragma unroll
                for (int q = 0; q < 4; q++) sacc[j][q] = 0.f;

            // S = Qh*Kh + Ql*Kh, merged: each b-tile loaded once
#pragma unroll
            for (int ks = 0; ks < 6; ks++) {
                uint32_t ah0, ah1, ah2, ah3, al0, al1, al2, al3;
                const uint32_t arow_off = (wid * 16 + a_row) * FROW + ks * 32 + a_cs;
                LDSM_X4(ah0, ah1, ah2, ah3, sQh_ + arow_off);
                LDSM_X4(al0, al1, al2, al3, sQl_ + arow_off);
#pragma unroll
                for (int p = 0; p < 4; p++) {
                    uint32_t b0, b1, b2, b3;
                    LDSM_X4(b0, b1, b2, b3,
                            sKh_ + (p * 16 + b_row) * FROW + ks * 32 + b_cs);
                    mma_f16(sacc[2 * p],     ah0, ah1, ah2, ah3, b0, b1);
                    mma_f16(sacc[2 * p + 1], ah0, ah1, ah2, ah3, b2, b3);
                    mma_f16(sacc[2 * p],     al0, al1, al2, al3, b0, b1);
                    mma_f16(sacc[2 * p + 1], al0, al1, al2, al3, b2, b3);
                }
            }

            if (key0 + FBN - 1 > qr_lo) {
#pragma unroll
                for (int j = 0; j < 8; j++) {
                    int kcol = key0 + 8 * j + (lane & 3) * 2;
                    if (kcol     > row0)     sacc[j][0] = -CUDART_INF_F;
                    if (kcol + 1 > row0)     sacc[j][1] = -CUDART_INF_F;
                    if (kcol     > row0 + 8) sacc[j][2] = -CUDART_INF_F;
                    if (kcol + 1 > row0 + 8) sacc[j][3] = -CUDART_INF_F;
                }
            }

            float mx0 = sacc[0][0], mx1 = sacc[0][2];
#pragma unroll
            for (int j = 0; j < 8; j++) {
                mx0 = fmaxf(mx0, fmaxf(sacc[j][0], sacc[j][1]));
                mx1 = fmaxf(mx1, fmaxf(sacc[j][2], sacc[j][3]));
            }
            mx0 = fmaxf(mx0, __shfl_xor_sync(0xffffffffu, mx0, 1));
            mx0 = fmaxf(mx0, __shfl_xor_sync(0xffffffffu, mx0, 2));
            mx1 = fmaxf(mx1, __shfl_xor_sync(0xffffffffu, mx1, 1));
            mx1 = fmaxf(mx1, __shfl_xor_sync(0xffffffffu, mx1, 2));

            float mn0 = fmaxf(m0, mx0), mn1 = fmaxf(m1, mx1);
            float al0 = __expf(m0 - mn0), al1 = __expf(m1 - mn1);

            uint32_t ph[8][2];
            float sum0 = 0.f, sum1 = 0.f;
#pragma unroll
            for (int j = 0; j < 8; j++) {
                float p0 = __expf(sacc[j][0] - mn0), p1 = __expf(sacc[j][1] - mn0);
                float p2 = __expf(sacc[j][2] - mn1), p3 = __expf(sacc[j][3] - mn1);
                sum0 += p0 + p1; sum1 += p2 + p3;
                __half2 h01 = __floats2half2_rn(p0, p1);
                __half2 h23 = __floats2half2_rn(p2, p3);
                ph[j][0] = *(uint32_t*)&h01;
                ph[j][1] = *(uint32_t*)&h23;
            }
            sum0 += __shfl_xor_sync(0xffffffffu, sum0, 1);
            sum0 += __shfl_xor_sync(0xffffffffu, sum0, 2);
            sum1 += __shfl_xor_sync(0xffffffffu, sum1, 1);
            sum1 += __shfl_xor_sync(0xffffffffu, sum1, 2);

            l0 = l0 * al0 + sum0;  l1 = l1 * al1 + sum1;
            m0 = mn0;              m1 = mn1;
#pragma unroll
            for (int j = 0; j < 12; j++) {
                oacc[j][0] *= al0; oacc[j][1] *= al0;
                oacc[j][2] *= al1; oacc[j][3] *= al1;
            }

            // O += Ph*Vh
#pragma unroll
            for (int kk = 0; kk < 4; kk++) {
                uint32_t a0 = ph[2 * kk][0], a1 = ph[2 * kk][1];
                uint32_t a2 = ph[2 * kk + 1][0], a3 = ph[2 * kk + 1][1];
#pragma unroll
                for (int p = 0; p < 6; p++) {
                    uint32_t vaddr = (16 * kk + t_row) * FROW + p * 32 + t_cs;
                    uint32_t b0, b1, b2, b3;
                    LDSM_X4_T(b0, b1, b2, b3, sVh_ + vaddr);
                    mma_f16(oacc[2 * p],     a0, a1, a2, a3, b0, b1);
                    mma_f16(oacc[2 * p + 1], a0, a1, a2, a3, b2, b3);
                }
            }
        }
        __syncthreads();
    }

    // epilogue: normalize + flat fp16 store (row = KP_O = QDIM)
    const float inv0 = 1.f / l0, inv1 = 1.f / l1;
    __half* ob0 = AOs + (size_t)row0 * KP_O + h * FD + (lane & 3) * 2;
    __half* ob1 = AOs + (size_t)(row0 + 8) * KP_O + h * FD + (lane & 3) * 2;
#pragma unroll
    for (int j = 0; j < 12; j++) {
        *(__half2*)(ob0 + j * 8) = __floats2half2_rn(oacc[j][0] * inv0, oacc[j][1] * inv0);
        *(__half2*)(ob1 + j * 8) = __floats2half2_rn(oacc[j][2] * inv1, oacc[j][3] * inv1);
    }
}

// ---------------------------------------------------------------------------
extern "C" void kernel_launch(void* const* d_in, const int* in_sizes, int n_in,
                              void* d_out, int out_size)
{
    const float* hs  = (const float*)d_in[0];
    const float* cs  = (const float*)d_in[1];
    const float* sn  = (const float*)d_in[2];
    const int*   idx = (const int*)  d_in[3];
    const float* Wq  = (const float*)d_in[4];
    const float* Wk  = (const float*)d_in[5];
    const float* Wv  = (const float*)d_in[6];
    const float* Wo  = (const float*)d_in[7];
    float* out = (float*)d_out;

    float *Qb, *Kb, *Vb;
    __half *hsb, *wqb, *wkb, *wvb, *aob, *wob;
    __half *qh, *ql, *kh, *vh;
    cudaGetSymbolAddress((void**)&Qb,  g_Q);
    cudaGetSymbolAddress((void**)&Kb,  g_K);
    cudaGetSymbolAddress((void**)&Vb,  g_V);
    cudaGetSymbolAddress((void**)&hsb, g_hsb);
    cudaGetSymbolAddress((void**)&wqb, g_wqb);
    cudaGetSymbolAddress((void**)&wkb, g_wkb);
    cudaGetSymbolAddress((void**)&wvb, g_wvb);
    cudaGetSymbolAddress((void**)&aob, g_aob);
    cudaGetSymbolAddress((void**)&wob, g_wob);
    cudaGetSymbolAddress((void**)&qh,  g_Qh);
    cudaGetSymbolAddress((void**)&ql,  g_Ql);
    cudaGetSymbolAddress((void**)&kh,  g_Kh);
    cudaGetSymbolAddress((void**)&vh,  g_Vh);

    static bool attr_set = false;
    if (!attr_set) {
        cudaFuncSetAttribute(gemm_mma,  cudaFuncAttributeMaxDynamicSharedMemorySize, GEMM_SMEM);
        cudaFuncSetAttribute(flash_mma, cudaFuncAttributeMaxDynamicSharedMemorySize, FLASH_SMEM);
        attr_set = true;
    }

    // fused flat fp16 conversions (one launch, float4-vectorized)
    {
        const int n0 = S_LEN * HIDDEN / 4;
        const int n1 = QDIM  * HIDDEN / 4;
        const int n2 = KVDIM * HIDDEN / 4;
        const int n3 = KVDIM * HIDDEN / 4;
        const int n4 = HIDDEN * QDIM  / 4;
        const int tot = n0 + n1 + n2 + n3 + n4;
        split_all<<<(tot + 255) / 256, 256>>>(
            hs, hsb, n0,
            Wq, wqb, n1,
            Wk, wkb, n2,
            Wv, wvb, n3,
            Wo, wob, n4);
    }

    // fused QKV projection (fp16 1-term, K = HIDDEN): 12+3+3 = 18 N-tiles
    gemm_mma<<<dim3(18, S_LEN / BM), 256, GEMM_SMEM>>>(
        hsb,
        wqb, Qb, QDIM / BN,  QDIM,
        wkb, Kb, KVDIM / BN, KVDIM,
        wvb, Vb,             KVDIM,
        KP_QKV);

    // fused RoPE+split (Q h/l, K h) + V fp16 convert, one launch
    {
        const int totQ = S_LEN * NH  * 48;
        const int totK = S_LEN * NKV * 48;
        const int totV = S_LEN * KVDIM / 2;
        const int tot = totQ + totK + totV;
        rope_split_all<<<(tot + 255) / 256, 256>>>(
            Qb, qh, ql, Kb, kh, Vb, vh, cs, sn, idx, totQ, totK, totV);
    }

    // causal GQA attention — writes flat fp16 AO
    flash_mma<<<dim3(S_LEN / FBM, NH), 256, FLASH_SMEM>>>(qh, ql, kh, vh, aob);

    // output projection (fp16 1-term) -> d_out: 16 N-tiles
    gemm_mma<<<dim3(HIDDEN / BN, S_LEN / BM), 256, GEMM_SMEM>>>(
        aob,
        wob, out, HIDDEN / BN, HIDDEN,
        wob, out, 0,           HIDDEN,
        wob, out,              HIDDEN,
        KP_O);
}

// round 17
// speedup vs baseline: 2.2925x; 2.2925x over previous
#include <cuda_runtime.h>
#include <cuda_bf16.h>
#include <cuda_fp16.h>
#include <math_constants.h>
#include <cstdint>

#define S_LEN  2048
#define HIDDEN 4096
#define NH     32
#define NKV    8
#define HD     96
#define GROUPS 4
#define QDIM   (NH * HD)    // 3072
#define KVDIM  (NKV * HD)   // 768
#define DFULL  128
#define ATT_SCALE 0.08838834764831845f  // 128^-0.5

#define KP_QKV HIDDEN         // 4096 (fp16 1-term)
#define KP_O   QDIM           // 3072 (fp16 1-term)

// ---------------- scratch (allocation-free: device globals) ----------------
static __device__ __align__(256) float g_Q [S_LEN * QDIM];
static __device__ __align__(256) float g_K [S_LEN * KVDIM];
static __device__ __align__(256) float g_V [S_LEN * KVDIM];

static __device__ __align__(256) __half g_hsb[S_LEN * KP_QKV];   // flat h
static __device__ __align__(256) __half g_wqb[QDIM * KP_QKV];    // flat h
static __device__ __align__(256) __half g_wkb[KVDIM * KP_QKV];
static __device__ __align__(256) __half g_wvb[KVDIM * KP_QKV];
static __device__ __align__(256) __half g_aob[S_LEN * KP_O];     // flat h
static __device__ __align__(256) __half g_wob[HIDDEN * KP_O];    // flat h

// flash operands (all fp16; Q keeps hi/lo)
static __device__ __align__(256) __half g_Qh[S_LEN * QDIM];
static __device__ __align__(256) __half g_Ql[S_LEN * QDIM];
static __device__ __align__(256) __half g_Kh[S_LEN * KVDIM];
static __device__ __align__(256) __half g_Vh[S_LEN * KVDIM];

// ---------------------------------------------------------------------------
// PTX helpers
// ---------------------------------------------------------------------------
__device__ __forceinline__ uint32_t smem_u32(const void* p) {
    uint32_t a;
    asm("{ .reg .u64 t; cvta.to.shared.u64 t, %1; cvt.u32.u64 %0, t; }" : "=r"(a) : "l"(p));
    return a;
}
#define CP_ASYNC16(dst, src) asm volatile("cp.async.cg.shared.global [%0], [%1], 16;" :: "r"(dst), "l"(src))
#define CP_COMMIT()          asm volatile("cp.async.commit_group;" ::: "memory")
#define CP_WAIT(n)           asm volatile("cp.async.wait_group %0;" :: "n"(n) : "memory")

#define LDSM_X4(r0, r1, r2, r3, addr)                                            \
    asm volatile("ldmatrix.sync.aligned.m8n8.x4.shared.b16 {%0,%1,%2,%3}, [%4];" \
        : "=r"(r0), "=r"(r1), "=r"(r2), "=r"(r3) : "r"(addr))

#define LDSM_X4_T(r0, r1, r2, r3, addr)                                                \
    asm volatile("ldmatrix.sync.aligned.m8n8.x4.trans.shared.b16 {%0,%1,%2,%3}, [%4];" \
        : "=r"(r0), "=r"(r1), "=r"(r2), "=r"(r3) : "r"(addr))

__device__ __forceinline__ void mma_f16(float* c, uint32_t a0, uint32_t a1,
                                        uint32_t a2, uint32_t a3,
                                        uint32_t b0, uint32_t b1) {
    asm volatile(
        "mma.sync.aligned.m16n8k16.row.col.f32.f16.f16.f32 "
        "{%0,%1,%2,%3}, {%4,%5,%6,%7}, {%8,%9}, {%0,%1,%2,%3};"
        : "+f"(c[0]), "+f"(c[1]), "+f"(c[2]), "+f"(c[3])
        : "r"(a0), "r"(a1), "r"(a2), "r"(a3), "r"(b0), "r"(b1));
}

// ---------------------------------------------------------------------------
// fp16 HMMA GEMM  (R15-proven configuration).
// BM=128, BN=128, BK=64, 2-stage cp.async pipeline, 4 warps, warp tile 64x64.
// launch_bounds(128,3) -> 3 CTAs/SM (regs 170, RF-feasible).
// ---------------------------------------------------------------------------
#define BM 128
#define BN 128
#define BKE 64
#define ROW_B 144
#define TILE_BYTES (128 * ROW_B)
#define STAGE_BYTES (2 * TILE_BYTES)
#define NSTAGE 2
#define GEMM_SMEM (NSTAGE * STAGE_BYTES)   // 73728

__device__ __forceinline__ void load_tiles(uint32_t stage_base,
    const __half* __restrict__ A, const __half* __restrict__ B,
    int bm, int bn, int kc, int Kp, int tid)
{
    const char* Ag = (const char*)(A + (size_t)bm * Kp + kc * BKE);
    const char* Bg = (const char*)(B + (size_t)bn * Kp + kc * BKE);
    const size_t rowb = (size_t)Kp * 2;
    const uint32_t sA = stage_base;
    const uint32_t sB = stage_base + TILE_BYTES;
#pragma unroll
    for (int i = 0; i < 8; i++) {
        int idx = tid + i * 128;
        int row = idx >> 3, seg = idx & 7;
        CP_ASYNC16(sA + row * ROW_B + seg * 16, Ag + (size_t)row * rowb + seg * 16);
    }
#pragma unroll
    for (int i = 0; i < 8; i++) {
        int idx = tid + i * 128;
        int row = idx >> 3, seg = idx & 7;
        CP_ASYNC16(sB + row * ROW_B + seg * 16, Bg + (size_t)row * rowb + seg * 16);
    }
}

__global__ __launch_bounds__(128, 3) void gemm_mma(
    const __half* __restrict__ A,
    const __half* __restrict__ B0, float* __restrict__ C0, int nt0, int N0,
    const __half* __restrict__ B1, float* __restrict__ C1, int nt1, int N1,
    const __half* __restrict__ B2, float* __restrict__ C2, int N2,
    int Kp)
{
    extern __shared__ char smem[];
    const uint32_t sbase = smem_u32(smem);
    const int tid  = threadIdx.x;
    const int wid  = tid >> 5;
    const int lane = tid & 31;
    const int bm   = blockIdx.y * BM;
    const int NC   = Kp / BKE;

    int bnt = blockIdx.x;
    const __half* B;
    float* C; int N;
    if (bnt < nt0)            { B = B0; C = C0; N = N0; }
    else if (bnt < nt0 + nt1) { B = B1; C = C1; N = N1; bnt -= nt0; }
    else                      { B = B2; C = C2; N = N2; bnt -= nt0 + nt1; }
    const int bn = bnt * BN;

    const int wm = (wid >> 1) * 64;
    const int wn = (wid & 1) * 64;

    float acc[4][8][4];
#pragma unroll
    for (int t = 0; t < 4; t++)
#pragma unroll
        for (int j = 0; j < 8; j++)
#pragma unroll
            for (int q = 0; q < 4; q++) acc[t][j][q] = 0.f;

    const int a_row    = ((lane >> 3) & 1) * 8 + (lane & 7);
    const int a_cshift = ((lane >> 4) & 1) * 16;
    const int b_row    = ((lane >> 4) & 1) * 8 + (lane & 7);
    const int b_cshift = ((lane >> 3) & 1) * 16;

    load_tiles(sbase, A, B, bm, bn, 0, Kp, tid); CP_COMMIT();

    for (int c = 0; c < NC; c++) {
        CP_WAIT(0);
        __syncthreads();

        if (c + 1 < NC) {
            load_tiles(sbase + ((c + 1) & 1) * STAGE_BYTES, A, B, bm, bn, c + 1, Kp, tid);
            CP_COMMIT();
        }

        const uint32_t sA = sbase + (c & 1) * STAGE_BYTES;
        const uint32_t sB = sA + TILE_BYTES;
#pragma unroll
        for (int ks = 0; ks < 4; ks++) {
            uint32_t a[4][4];
#pragma unroll
            for (int t = 0; t < 4; t++) {
                uint32_t addr = sA + (wm + t * 16 + a_row) * ROW_B + ks * 32 + a_cshift;
                LDSM_X4(a[t][0], a[t][1], a[t][2], a[t][3], addr);
            }
#pragma unroll
            for (int p = 0; p < 4; p++) {
                uint32_t b0, b1, b2, b3;
                uint32_t addr = sB + (wn + p * 16 + b_row) * ROW_B + ks * 32 + b_cshift;
                LDSM_X4(b0, b1, b2, b3, addr);
#pragma unroll
                for (int t = 0; t < 4; t++) {
                    mma_f16(acc[t][2 * p],     a[t][0], a[t][1], a[t][2], a[t][3], b0, b1);
                    mma_f16(acc[t][2 * p + 1], a[t][0], a[t][1], a[t][2], a[t][3], b2, b3);
                }
            }
        }
    }

#pragma unroll
    for (int t = 0; t < 4; t++) {
        const int r0 = bm + wm + t * 16 + (lane >> 2);
#pragma unroll
        for (int j = 0; j < 8; j++) {
            const int col = bn + wn + j * 8 + (lane & 3) * 2;
            float* c0 = C + (size_t)r0 * N + col;
            float* c1 = C + (size_t)(r0 + 8) * N + col;
            *(float2*)c0 = make_float2(acc[t][j][0], acc[t][j][1]);
            *(float2*)c1 = make_float2(acc[t][j][2], acc[t][j][3]);
        }
    }
}

// ---------------------------------------------------------------------------
// Fused flat fp32 -> fp16 conversions over 5 regions, float4-vectorized.
// ---------------------------------------------------------------------------
__global__ void split_all(const float* __restrict__ x0, __half* y0, int n0,
                          const float* __restrict__ x1, __half* y1, int n1,
                          const float* __restrict__ x2, __half* y2, int n2,
                          const float* __restrict__ x3, __half* y3, int n3,
                          const float* __restrict__ x4, __half* y4, int n4)
{
    int t = blockIdx.x * blockDim.x + threadIdx.x;   // quad index
    const float* X; __half* Y;
    if      (t < n0)         { X = x0; Y = y0; }
    else if ((t -= n0) < n1) { X = x1; Y = y1; }
    else if ((t -= n1) < n2) { X = x2; Y = y2; }
    else if ((t -= n2) < n3) { X = x3; Y = y3; }
    else if ((t -= n3) < n4) { X = x4; Y = y4; }
    else return;
    float4 x = ((const float4*)X)[t];
    __half2 h0 = __floats2half2_rn(x.x, x.y);
    __half2 h1 = __floats2half2_rn(x.z, x.w);
    uint2 v;
    v.x = *(uint32_t*)&h0;
    v.y = *(uint32_t*)&h1;
    ((uint2*)Y)[t] = v;
}

// ---------------------------------------------------------------------------
// Fused indexed RoPE (fp16 out) + V fp16 convert, one launch.
// Q: hi/lo fp16 split (scaled); K: hi only.
// ---------------------------------------------------------------------------
__device__ __forceinline__ void do_rope(const float* X,
                                        __half* Xh, __half* Xl, bool write_lo,
                                        const float* cosT, const float* sinT,
                                        const int* idx, int nheads, int group,
                                        float scale, int t)
{
    int d = t % 48;
    int h = (t / 48) % nheads;
    int s = t / (48 * nheads);
    int hk = h / group;

    const float* base = X + (size_t)s * (nheads * HD) + h * HD;
    float x1 = base[d];
    float x2 = base[d + 48];

    int i1 = idx[hk * HD + d];
    int i2 = idx[hk * HD + d + 48];
    float c1 = cosT[s * DFULL + i1], s1 = sinT[s * DFULL + i1];
    float c2 = cosT[s * DFULL + i2], s2 = sinT[s * DFULL + i2];

    float lo = (x1 * c1 - x2 * s1) * scale;
    float hi = (x2 * c2 + x1 * s2) * scale;

    size_t o = (size_t)s * (nheads * HD) + h * HD;
    __half bh = __float2half_rn(lo);
    Xh[o + d] = bh;
    if (write_lo) Xl[o + d] = __float2half_rn(lo - __half2float(bh));
    bh = __float2half_rn(hi);
    Xh[o + d + 48] = bh;
    if (write_lo) Xl[o + d + 48] = __float2half_rn(hi - __half2float(bh));
}

__global__ void rope_split_all(
    const float* __restrict__ Qs, __half* Qh, __half* Ql,
    const float* __restrict__ Ks, __half* Kh,
    const float* __restrict__ Vs, __half* Vh,
    const float* __restrict__ cosT, const float* __restrict__ sinT,
    const int* __restrict__ idx, int totQ, int totK, int totVpairs)
{
    int t = blockIdx.x * blockDim.x + threadIdx.x;
    if (t < totQ) {
        do_rope(Qs, Qh, Ql, true, cosT, sinT, idx, NH, GROUPS, ATT_SCALE, t);
        return;
    }
    t -= totQ;
    if (t < totK) {
        do_rope(Ks, Kh, nullptr, false, cosT, sinT, idx, NKV, 1, 1.0f, t);
        return;
    }
    t -= totK;
    if (t < totVpairs) {
        float2 x = ((const float2*)Vs)[t];
        __half2 h = __floats2half2_rn(x.x, x.y);
        ((uint32_t*)Vh)[t] = *(uint32_t*)&h;
    }
}

// ---------------------------------------------------------------------------
// fp16 HMMA flash attention, causal GQA. CTA = 128 q-rows x 1 head, 8 warps.
// 64-key blocks, double-buffered cp.async KV stages (Kh + Vh fp16).
// S = QhKh + QlKh (merged passes);  O += PhVh.  Flat fp16 AO out.
// launch_bounds(256,2) -> target 2 CTAs/SM (live set ~120 regs fits 128 cap).
// ---------------------------------------------------------------------------
#define FD   96
#define FBM  128
#define FBN  64
#define FROW 208
#define FQ_BYTES  (FBM * FROW)
#define FKV_BYTES (FBN * FROW)
#define STG_BYTES (2 * FKV_BYTES)
#define FLASH_SMEM (2 * FQ_BYTES + 2 * STG_BYTES)   // 106496

__device__ __forceinline__ void flash_load_kv(uint32_t st_base,
    const __half* Kh, const __half* Vh, int key0, int hk, int tid)
{
    const size_t goff = (size_t)key0 * (KVDIM * 2) + hk * (FD * 2);
    const char* g0 = (const char*)Kh + goff;
    const char* g1 = (const char*)Vh + goff;
#pragma unroll
    for (int i = 0; i < 3; i++) {
        int idx = tid + i * 256;
        int row = idx / 12, seg = idx - row * 12;
        uint32_t d = st_base + row * FROW + seg * 16;
        size_t go = (size_t)row * (KVDIM * 2) + seg * 16;
        CP_ASYNC16(d,             g0 + go);
        CP_ASYNC16(d + FKV_BYTES, g1 + go);
    }
}

__global__ __launch_bounds__(256, 2) void flash_mma(
    const __half* __restrict__ Qh, const __half* __restrict__ Ql,
    const __half* __restrict__ Kh, const __half* __restrict__ Vh,
    __half* __restrict__ AOs)
{
    extern __shared__ char smem[];
    const uint32_t sb = smem_u32(smem);
    const int tid = threadIdx.x, wid = tid >> 5, lane = tid & 31;
    const int h = blockIdx.y, hk = h / GROUPS;
    const int qbase = ((int)gridDim.x - 1 - (int)blockIdx.x) * FBM;  // heavy first
    const int nb = qbase / FBN + 2;

    const uint32_t sQh_ = sb, sQl_ = sb + FQ_BYTES;
    const uint32_t st0 = sb + 2 * FQ_BYTES;

    {
        const char* gqh = (const char*)(Qh + (size_t)qbase * QDIM + h * FD);
        const char* gql = (const char*)(Ql + (size_t)qbase * QDIM + h * FD);
#pragma unroll
        for (int i = 0; i < 6; i++) {
            int idx = tid + i * 256;
            int row = idx / 12, seg = idx - row * 12;
            uint32_t d = row * FROW + seg * 16;
            size_t go = (size_t)row * (QDIM * 2) + seg * 16;
            CP_ASYNC16(sQh_ + d, gqh + go);
            CP_ASYNC16(sQl_ + d, gql + go);
        }
        flash_load_kv(st0, Kh, Vh, 0, hk, tid);
        CP_COMMIT();
    }

    float oacc[12][4];
#pragma unroll
    for (int j = 0; j < 12; j++)
#pragma unroll
        for (int q = 0; q < 4; q++) oacc[j][q] = 0.f;
    float m0 = -CUDART_INF_F, m1 = -CUDART_INF_F, l0 = 0.f, l1 = 0.f;

    const int a_row = (lane & 7) + ((lane >> 3) & 1) * 8;
    const int a_cs  = ((lane >> 4) & 1) * 16;
    const int b_row = (lane & 7) + ((lane >> 4) & 1) * 8;
    const int b_cs  = ((lane >> 3) & 1) * 16;
    const int t_row = (lane & 7) + ((lane >> 3) & 1) * 8;
    const int t_cs  = ((lane >> 4) & 1) * 16;

    const int qr_lo = qbase + wid * 16;
    const int row0  = qr_lo + (lane >> 2);

    for (int kb = 0; kb < nb; kb++) {
        if (kb + 1 < nb) {
            flash_load_kv(st0 + ((kb + 1) & 1) * STG_BYTES, Kh, Vh,
                          (kb + 1) * FBN, hk, tid);
            CP_COMMIT();
            CP_WAIT(1);
        } else {
            CP_WAIT(0);
        }
        __syncthreads();

        const int key0 = kb * FBN;
        if (key0 <= qr_lo + 15) {
            const uint32_t sKh_ = st0 + (kb & 1) * STG_BYTES;
            const uint32_t sVh_ = sKh_ + FKV_BYTES;

            float sacc[8][4];
#pragma unroll
            for (int j = 0; j < 8; j++)
#pragma unroll
                for (int q = 0; q < 4; q++) sacc[j][q] = 0.f;

            // S = Qh*Kh + Ql*Kh, merged: each b-tile loaded once
#pragma unroll
            for (int ks = 0; ks < 6; ks++) {
                uint32_t ah0, ah1, ah2, ah3, al0, al1, al2, al3;
                const uint32_t arow_off = (wid * 16 + a_row) * FROW + ks * 32 + a_cs;
                LDSM_X4(ah0, ah1, ah2, ah3, sQh_ + arow_off);
                LDSM_X4(al0, al1, al2, al3, sQl_ + arow_off);
#pragma unroll
                for (int p = 0; p < 4; p++) {
                    uint32_t b0, b1, b2, b3;
                    LDSM_X4(b0, b1, b2, b3,
                            sKh_ + (p * 16 + b_row) * FROW + ks * 32 + b_cs);
                    mma_f16(sacc[2 * p],     ah0, ah1, ah2, ah3, b0, b1);
                    mma_f16(sacc[2 * p + 1], ah0, ah1, ah2, ah3, b2, b3);
                    mma_f16(sacc[2 * p],     al0, al1, al2, al3, b0, b1);
                    mma_f16(sacc[2 * p + 1], al0, al1, al2, al3, b2, b3);
                }
            }

            if (key0 + FBN - 1 > qr_lo) {
#pragma unroll
                for (int j = 0; j < 8; j++) {
                    int kcol = key0 + 8 * j + (lane & 3) * 2;
                    if (kcol     > row0)     sacc[j][0] = -CUDART_INF_F;
                    if (kcol + 1 > row0)     sacc[j][1] = -CUDART_INF_F;
                    if (kcol     > row0 + 8) sacc[j][2] = -CUDART_INF_F;
                    if (kcol + 1 > row0 + 8) sacc[j][3] = -CUDART_INF_F;
                }
            }

            float mx0 = sacc[0][0], mx1 = sacc[0][2];
#pragma unroll
            for (int j = 0; j < 8; j++) {
                mx0 = fmaxf(mx0, fmaxf(sacc[j][0], sacc[j][1]));
                mx1 = fmaxf(mx1, fmaxf(sacc[j][2], sacc[j][3]));
            }
            mx0 = fmaxf(mx0, __shfl_xor_sync(0xffffffffu, mx0, 1));
            mx0 = fmaxf(mx0, __shfl_xor_sync(0xffffffffu, mx0, 2));
            mx1 = fmaxf(mx1, __shfl_xor_sync(0xffffffffu, mx1, 1));
            mx1 = fmaxf(mx1, __shfl_xor_sync(0xffffffffu, mx1, 2));

            float mn0 = fmaxf(m0, mx0), mn1 = fmaxf(m1, mx1);
            float al0 = __expf(m0 - mn0), al1 = __expf(m1 - mn1);

            uint32_t ph[8][2];
            float sum0 = 0.f, sum1 = 0.f;
#pragma unroll
            for (int j = 0; j < 8; j++) {
                float p0 = __expf(sacc[j][0] - mn0), p1 = __expf(sacc[j][1] - mn0);
                float p2 = __expf(sacc[j][2] - mn1), p3 = __expf(sacc[j][3] - mn1);
                sum0 += p0 + p1; sum1 += p2 + p3;
                __half2 h01 = __floats2half2_rn(p0, p1);
                __half2 h23 = __floats2half2_rn(p2, p3);
                ph[j][0] = *(uint32_t*)&h01;
                ph[j][1] = *(uint32_t*)&h23;
            }
            sum0 += __shfl_xor_sync(0xffffffffu, sum0, 1);
            sum0 += __shfl_xor_sync(0xffffffffu, sum0, 2);
            sum1 += __shfl_xor_sync(0xffffffffu, sum1, 1);
            sum1 += __shfl_xor_sync(0xffffffffu, sum1, 2);

            l0 = l0 * al0 + sum0;  l1 = l1 * al1 + sum1;
            m0 = mn0;              m1 = mn1;
#pragma unroll
            for (int j = 0; j < 12; j++) {
                oacc[j][0] *= al0; oacc[j][1] *= al0;
                oacc[j][2] *= al1; oacc[j][3] *= al1;
            }

            // O += Ph*Vh
#pragma unroll
            for (int kk = 0; kk < 4; kk++) {
                uint32_t a0 = ph[2 * kk][0], a1 = ph[2 * kk][1];
                uint32_t a2 = ph[2 * kk + 1][0], a3 = ph[2 * kk + 1][1];
#pragma unroll
                for (int p = 0; p < 6; p++) {
                    uint32_t vaddr = (16 * kk + t_row) * FROW + p * 32 + t_cs;
                    uint32_t b0, b1, b2, b3;
                    LDSM_X4_T(b0, b1, b2, b3, sVh_ + vaddr);
                    mma_f16(oacc[2 * p],     a0, a1, a2, a3, b0, b1);
                    mma_f16(oacc[2 * p + 1], a0, a1, a2, a3, b2, b3);
                }
            }
        }
        __syncthreads();
    }

    // epilogue: normalize + flat fp16 store (row = KP_O = QDIM)
    const float inv0 = 1.f / l0, inv1 = 1.f / l1;
    __half* ob0 = AOs + (size_t)row0 * KP_O + h * FD + (lane & 3) * 2;
    __half* ob1 = AOs + (size_t)(row0 + 8) * KP_O + h * FD + (lane & 3) * 2;
#pragma unroll
    for (int j = 0; j < 12; j++) {
        *(__half2*)(ob0 + j * 8) = __floats2half2_rn(oacc[j][0] * inv0, oacc[j][1] * inv0);
        *(__half2*)(ob1 + j * 8) = __floats2half2_rn(oacc[j][2] * inv1, oacc[j][3] * inv1);
    }
}

// ---------------------------------------------------------------------------
extern "C" void kernel_launch(void* const* d_in, const int* in_sizes, int n_in,
                              void* d_out, int out_size)
{
    const float* hs  = (const float*)d_in[0];
    const float* cs  = (const float*)d_in[1];
    const float* sn  = (const float*)d_in[2];
    const int*   idx = (const int*)  d_in[3];
    const float* Wq  = (const float*)d_in[4];
    const float* Wk  = (const float*)d_in[5];
    const float* Wv  = (const float*)d_in[6];
    const float* Wo  = (const float*)d_in[7];
    float* out = (float*)d_out;

    float *Qb, *Kb, *Vb;
    __half *hsb, *wqb, *wkb, *wvb, *aob, *wob;
    __half *qh, *ql, *kh, *vh;
    cudaGetSymbolAddress((void**)&Qb,  g_Q);
    cudaGetSymbolAddress((void**)&Kb,  g_K);
    cudaGetSymbolAddress((void**)&Vb,  g_V);
    cudaGetSymbolAddress((void**)&hsb, g_hsb);
    cudaGetSymbolAddress((void**)&wqb, g_wqb);
    cudaGetSymbolAddress((void**)&wkb, g_wkb);
    cudaGetSymbolAddress((void**)&wvb, g_wvb);
    cudaGetSymbolAddress((void**)&aob, g_aob);
    cudaGetSymbolAddress((void**)&wob, g_wob);
    cudaGetSymbolAddress((void**)&qh,  g_Qh);
    cudaGetSymbolAddress((void**)&ql,  g_Ql);
    cudaGetSymbolAddress((void**)&kh,  g_Kh);
    cudaGetSymbolAddress((void**)&vh,  g_Vh);

    static bool attr_set = false;
    if (!attr_set) {
        cudaFuncSetAttribute(gemm_mma,  cudaFuncAttributeMaxDynamicSharedMemorySize, GEMM_SMEM);
        cudaFuncSetAttribute(flash_mma, cudaFuncAttributeMaxDynamicSharedMemorySize, FLASH_SMEM);
        attr_set = true;
    }

    // fused flat fp16 conversions (one launch, float4-vectorized)
    {
        const int n0 = S_LEN * HIDDEN / 4;
        const int n1 = QDIM  * HIDDEN / 4;
        const int n2 = KVDIM * HIDDEN / 4;
        const int n3 = KVDIM * HIDDEN / 4;
        const int n4 = HIDDEN * QDIM  / 4;
        const int tot = n0 + n1 + n2 + n3 + n4;
        split_all<<<(tot + 255) / 256, 256>>>(
            hs, hsb, n0,
            Wq, wqb, n1,
            Wk, wkb, n2,
            Wv, wvb, n3,
            Wo, wob, n4);
    }

    // fused QKV projection (fp16 1-term, K = HIDDEN): 24+6+6 = 36 N-tiles
    gemm_mma<<<dim3(36, S_LEN / BM), 128, GEMM_SMEM>>>(
        hsb,
        wqb, Qb, QDIM / BN,  QDIM,
        wkb, Kb, KVDIM / BN, KVDIM,
        wvb, Vb,             KVDIM,
        KP_QKV);

    // fused RoPE+split (Q h/l, K h) + V fp16 convert, one launch
    {
        const int totQ = S_LEN * NH  * 48;
        const int totK = S_LEN * NKV * 48;
        const int totV = S_LEN * KVDIM / 2;
        const int tot = totQ + totK + totV;
        rope_split_all<<<(tot + 255) / 256, 256>>>(
            Qb, qh, ql, Kb, kh, Vb, vh, cs, sn, idx, totQ, totK, totV);
    }

    // causal GQA attention — writes flat fp16 AO
    flash_mma<<<dim3(S_LEN / FBM, NH), 256, FLASH_SMEM>>>(qh, ql, kh, vh, aob);

    // output projection (fp16 1-term) -> d_out: 32 N-tiles
    gemm_mma<<<dim3(HIDDEN / BN, S_LEN / BM), 128, GEMM_SMEM>>>(
        aob,
        wob, out, HIDDEN / BN, HIDDEN,
        wob, out, 0,           HIDDEN,
        wob, out,              HIDDEN,
        KP_O);
}